// round 9
// baseline (speedup 1.0000x reference)
#include <cuda_runtime.h>

// ConvNearestNeightbor: out[b, n*C+c, h, w] = max_k |x_pad[b,c,h-row,w-col] - nb[n,c,k]|
// R9: all variants pin at ~14.2us ncu with issue ~70%, pipes ~30% -> empty issue slots
// from phased fma(subs)/alu(max-tree) bursts. Fuse two independent n-iterations at
// statement level so A's alu phase overlaps B's fma phase in one scheduling window.

namespace {

constexpr int B = 16, C = 32, H = 32, W = 32, NUM = 32;
constexpr int HW = H * W;
constexpr int NSPLIT = 2;
constexpr int NPER = NUM / NSPLIT;  // 16

// max(|a|,|b|) -> single FMNMX with |src| modifiers on both operands (alu pipe)
__device__ __forceinline__ float maxabs(float a, float b) {
  return fmaxf(fabsf(a), fabsf(b));
}

__global__ __launch_bounds__(256) void cnn_kernel(
    const float* __restrict__ x,
    const float* __restrict__ nb,
    float* __restrict__ out) {
  __shared__ __align__(16) float xs[34 * 36];      // halo tile, padded rows (36 floats)
  __shared__ __align__(16) float nbs[NPER * 12];   // 9 taps padded to 12 -> LDS.128

  const int bc = blockIdx.x;   // 0 .. B*C-1
  const int ns = blockIdx.y;   // 0 .. NSPLIT-1
  const int c  = bc & (C - 1);
  const int b  = bc / C;
  const int tid = threadIdx.x;

  const int h  = tid >> 3;          // 0..31
  const int wq = (tid & 7) << 2;    // 0,4,...,28

  // ---- neighbors first (latency hides under the x-tile load) ----
  if (tid < NPER * 9) {  // 144 scalars
    int nn = tid / 9;
    int k  = tid - nn * 9;
    nbs[nn * 12 + k] = nb[(size_t)(ns * NPER + nn) * (C * 9) + c * 9 + k];
  }

  // ---- x tile: 1 vector LDG per thread + predicated halo zeros ----
  const float* xp = x + (size_t)bc * HW;
  {
    float4 v = *(const float4*)(xp + h * W + wq);
    float* dst = &xs[(h + 1) * 36 + wq + 1];
    dst[0] = v.x; dst[1] = v.y; dst[2] = v.z; dst[3] = v.w;
  }
  if (tid < 132) {  // halo cells
    int rr, cc;
    if (tid < 68)        { rr = (tid < 34) ? 0 : 33; cc = (tid < 34) ? tid : tid - 34; }
    else if (tid < 100)  { rr = tid - 68 + 1;  cc = 0; }
    else                 { rr = tid - 100 + 1; cc = 33; }
    xs[rr * 36 + cc] = 0.f;
  }
  __syncthreads();

  // hoist the 3x6 x-window into registers (reused across all NPER n)
  float xv[3][6];
#pragma unroll
  for (int r = 0; r < 3; r++) {
    const float* p = &xs[(h + r) * 36 + wq];
    float4 v4 = *(const float4*)p;
    float2 v2 = *(const float2*)(p + 4);
    xv[r][0] = v4.x; xv[r][1] = v4.y; xv[r][2] = v4.z; xv[r][3] = v4.w;
    xv[r][4] = v2.x; xv[r][5] = v2.y;
  }

  float* const outp =
      out + ((size_t)(b * NUM + ns * NPER) * C + c) * HW + h * W + wq;

  // ---- fused pairs of independent n-iterations (A = 2p, B = 2p+1) ----
#pragma unroll
  for (int np = 0; np < NPER / 2; np++) {
    const int na = 2 * np, nbi = 2 * np + 1;
    float4 a0 = *(const float4*)&nbs[na * 12];
    float4 a1 = *(const float4*)&nbs[na * 12 + 4];
    float  a8 = nbs[na * 12 + 8];
    float4 b0 = *(const float4*)&nbs[nbi * 12];
    float4 b1 = *(const float4*)&nbs[nbi * 12 + 4];
    float  b8 = nbs[nbi * 12 + 8];
    const float nvA[9] = {a0.x, a0.y, a0.z, a0.w, a1.x, a1.y, a1.z, a1.w, a8};
    const float nvB[9] = {b0.x, b0.y, b0.z, b0.w, b1.x, b1.y, b1.z, b1.w, b8};

    float resA[4], resB[4];
#pragma unroll
    for (int j = 0; j < 4; j++) {
      // A and B diffs emitted adjacently: B's fma-pipe subs can fill slots
      // while A's alu-pipe max tree drains, and vice versa.
      float dA[9], dB[9];
#pragma unroll
      for (int k = 0; k < 9; k++) {
        const int r  = 2 - k / 3;
        const int cc = 2 - k % 3;
        const float xvv = xv[r][cc + j];
        dA[k] = xvv - nvA[k];
        dB[k] = xvv - nvB[k];
      }
      float ta0 = maxabs(dA[0], dA[1]);
      float tb0 = maxabs(dB[0], dB[1]);
      float ta1 = maxabs(dA[2], dA[3]);
      float tb1 = maxabs(dB[2], dB[3]);
      float ta2 = maxabs(dA[4], dA[5]);
      float tb2 = maxabs(dB[4], dB[5]);
      float ta3 = maxabs(dA[6], dA[7]);
      float tb3 = maxabs(dB[6], dB[7]);
      float ua0 = fmaxf(ta0, ta1);
      float ub0 = fmaxf(tb0, tb1);
      float ua1 = fmaxf(ta2, ta3);
      float ub1 = fmaxf(tb2, tb3);
      resA[j] = fmaxf(ua0, fmaxf(ua1, fabsf(dA[8])));
      resB[j] = fmaxf(ub0, fmaxf(ub1, fabsf(dB[8])));
    }
    // immediate-offset STGs, no pointer-increment chain
    *(float4*)(outp + (size_t)na  * C * HW) = make_float4(resA[0], resA[1], resA[2], resA[3]);
    *(float4*)(outp + (size_t)nbi * C * HW) = make_float4(resB[0], resB[1], resB[2], resB[3]);
  }
}

}  // namespace

extern "C" void kernel_launch(void* const* d_in, const int* in_sizes, int n_in,
                              void* d_out, int out_size) {
  const float* x  = (const float*)d_in[0];   // (B,C,H,W) fp32
  const float* nb = (const float*)d_in[1];   // (NUM,C,9) fp32
  float* out = (float*)d_out;                // (B, NUM*C, H, W) fp32
  dim3 grid(B * C, NSPLIT);
  cnn_kernel<<<grid, 256>>>(x, nb, out);
}

// round 10
// speedup vs baseline: 1.0216x; 1.0216x over previous
#include <cuda_runtime.h>

// ConvNearestNeightbor: out[b, n*C+c, h, w] = max_k |x_pad[b,c,h-row,w-col] - nb[n,c,k]|
// R10 model: fma-pipe demand 15.9K cyc/SMSP + alu 14.2K. Phase-serialized = 30K ~ measured
// 27K; overlapped = 16K (~8.5us). Tree-form lets ptxas batch all FADDs -> phases.
// Fix: RUNNING max (d = x-nk; m = max(m,|d|)) so each FMNMX consumes its FADD
// immediately; register pressure then forces 1:1 fma/alu interleave. 8 independent
// chains (4 outputs x 2 fused n) hide the lat-4 serial FMNMX chain.

namespace {

constexpr int B = 16, C = 32, H = 32, W = 32, NUM = 32;
constexpr int HW = H * W;
constexpr int NSPLIT = 2;
constexpr int NPER = NUM / NSPLIT;  // 16

// max(|a|,|b|) -> single FMNMX, both |src| modifiers
__device__ __forceinline__ float maxabs(float a, float b) {
  return fmaxf(fabsf(a), fabsf(b));
}

__global__ __launch_bounds__(256) void cnn_kernel(
    const float* __restrict__ x,
    const float* __restrict__ nb,
    float* __restrict__ out) {
  __shared__ __align__(16) float xs[34 * 36];      // halo tile, padded rows
  __shared__ __align__(16) float nbs[NPER * 12];   // 9 taps padded to 12 -> LDS.128

  const int bc = blockIdx.x;   // 0 .. B*C-1
  const int ns = blockIdx.y;   // 0 .. NSPLIT-1
  const int c  = bc & (C - 1);
  const int b  = bc / C;
  const int tid = threadIdx.x;

  const int h  = tid >> 3;          // 0..31
  const int wq = (tid & 7) << 2;    // 0,4,...,28

  // ---- neighbors first (latency hides under the x-tile load) ----
  if (tid < NPER * 9) {
    int nn = tid / 9;
    int k  = tid - nn * 9;
    nbs[nn * 12 + k] = nb[(size_t)(ns * NPER + nn) * (C * 9) + c * 9 + k];
  }

  // ---- x tile: 1 vector LDG per thread + predicated halo zeros ----
  const float* xp = x + (size_t)bc * HW;
  {
    float4 v = *(const float4*)(xp + h * W + wq);
    float* dst = &xs[(h + 1) * 36 + wq + 1];
    dst[0] = v.x; dst[1] = v.y; dst[2] = v.z; dst[3] = v.w;
  }
  if (tid < 132) {  // halo cells
    int rr, cc;
    if (tid < 68)        { rr = (tid < 34) ? 0 : 33; cc = (tid < 34) ? tid : tid - 34; }
    else if (tid < 100)  { rr = tid - 68 + 1;  cc = 0; }
    else                 { rr = tid - 100 + 1; cc = 33; }
    xs[rr * 36 + cc] = 0.f;
  }
  __syncthreads();

  // hoist the 3x6 x-window into registers (reused across all NPER n)
  float xv[3][6];
#pragma unroll
  for (int r = 0; r < 3; r++) {
    const float* p = &xs[(h + r) * 36 + wq];
    float4 v4 = *(const float4*)p;
    float2 v2 = *(const float2*)(p + 4);
    xv[r][0] = v4.x; xv[r][1] = v4.y; xv[r][2] = v4.z; xv[r][3] = v4.w;
    xv[r][4] = v2.x; xv[r][5] = v2.y;
  }

  float* const outp =
      out + ((size_t)(b * NUM + ns * NPER) * C + c) * HW + h * W + wq;

  // ---- fused pairs (A = 2p, B = 2p+1), running-max form ----
#pragma unroll
  for (int np = 0; np < NPER / 2; np++) {
    const int na = 2 * np, nbi = 2 * np + 1;
    float4 a0 = *(const float4*)&nbs[na * 12];
    float4 a1 = *(const float4*)&nbs[na * 12 + 4];
    float  a8 = nbs[na * 12 + 8];
    float4 b0 = *(const float4*)&nbs[nbi * 12];
    float4 b1 = *(const float4*)&nbs[nbi * 12 + 4];
    float  b8 = nbs[nbi * 12 + 8];
    const float nvA[9] = {a0.x, a0.y, a0.z, a0.w, a1.x, a1.y, a1.z, a1.w, a8};
    const float nvB[9] = {b0.x, b0.y, b0.z, b0.w, b1.x, b1.y, b1.z, b1.w, b8};

    float mA[4], mB[4];

    // k = 0,1: seed the running max with one dual-abs FMNMX per chain
#pragma unroll
    for (int j = 0; j < 4; j++) {
      // tap k -> coords: r = 2-k/3, cc = 2-k%3 ; k=0 -> (2,2), k=1 -> (2,1)
      float dA0 = xv[2][2 + j] - nvA[0];
      float dA1 = xv[2][1 + j] - nvA[1];
      mA[j] = maxabs(dA0, dA1);
      float dB0 = xv[2][2 + j] - nvB[0];
      float dB1 = xv[2][1 + j] - nvB[1];
      mB[j] = maxabs(dB0, dB1);
    }

    // k = 2..8: running max, FADD->FMNMX immediately (8 independent chains)
#pragma unroll
    for (int k = 2; k < 9; k++) {
      const int r  = 2 - k / 3;
      const int cc = 2 - k % 3;
#pragma unroll
      for (int j = 0; j < 4; j++) {
        float dA = xv[r][cc + j] - nvA[k];
        mA[j] = fmaxf(mA[j], fabsf(dA));
        float dB = xv[r][cc + j] - nvB[k];
        mB[j] = fmaxf(mB[j], fabsf(dB));
      }
    }

    *(float4*)(outp + (size_t)na  * C * HW) = make_float4(mA[0], mA[1], mA[2], mA[3]);
    *(float4*)(outp + (size_t)nbi * C * HW) = make_float4(mB[0], mB[1], mB[2], mB[3]);
  }
}

}  // namespace

extern "C" void kernel_launch(void* const* d_in, const int* in_sizes, int n_in,
                              void* d_out, int out_size) {
  const float* x  = (const float*)d_in[0];   // (B,C,H,W) fp32
  const float* nb = (const float*)d_in[1];   // (NUM,C,9) fp32
  float* out = (float*)d_out;                // (B, NUM*C, H, W) fp32
  dim3 grid(B * C, NSPLIT);
  cnn_kernel<<<grid, 256>>>(x, nb, out);
}